// round 10
// baseline (speedup 1.0000x reference)
#include <cuda_runtime.h>
#include <cstdint>

// Problem constants (STGNN_91242285236402): B=8, T=16, N=64, F=16, H=128
#define Bc 8
#define Tc 16
#define Nc 64
#define Fc 16
#define Hc 128
#define BN (Bc * Nc)   // 512
#define GRID 64
#define NTHR 512
#define CLUSTER 8

// 4-way ILP dot of two 16-float register tiles (float4 x4 each)
__device__ __forceinline__ float dot16(const float4* n, const float4& w0,
                                       const float4& w1, const float4& w2,
                                       const float4& w3)
{
    float p0 = n[0].x*w0.x + n[0].y*w0.y + n[0].z*w0.z + n[0].w*w0.w;
    float p1 = n[1].x*w1.x + n[1].y*w1.y + n[1].z*w1.z + n[1].w*w1.w;
    float p2 = n[2].x*w2.x + n[2].y*w2.y + n[2].z*w2.z + n[2].w*w2.w;
    float p3 = n[3].x*w3.x + n[3].y*w3.y + n[3].z*w3.z + n[3].w*w3.w;
    return (p0 + p1) + (p2 + p3);
}

// ---------------------------------------------------------------------------
// One fused kernel: 64 blocks x 512 threads, clusters of 8 (one per batch).
// Block rank c owns src rows s = c*8 .. c*8+7 of its batch b.
//   pre-arrive : node[8][128]; btT GEMM (W1t) -> DSMEM multicast into all 8
//                CTAs' bt4_sh (k-vectorized [k>>2][n][k&3]); rank0 inits out.
//   arrive     : barrier.cluster.arrive (hardware, per-batch)
//   hidden work: a GEMM (W1s) -> a_sh; wvec partials; lp (cb folded inline);
//                w2 stage; pr init
//   wait       : barrier.cluster.wait
//   post       : dense edge loop over local smem:
//     ew(s,t) = b2 + sum_k relu(a[s,k] + btT[k,t]) * W2[k], e = s*63+(t-(t>s))
//     pressures[b,t] += ew * lp[s]
// ---------------------------------------------------------------------------
__global__ void __launch_bounds__(NTHR, 1) __cluster_dims__(CLUSTER, 1, 1)
kfused(
    const float* __restrict__ x,   const float* __restrict__ Wg,
    const float* __restrict__ bg,  const float* __restrict__ W1,
    const float* __restrict__ b1,  const float* __restrict__ W2,
    const float* __restrict__ b2,  const float* __restrict__ Wgcn,
    const float* __restrict__ bgcn,const float* __restrict__ Wp,
    const float* __restrict__ bp,  float* __restrict__ out, int E)
{
    __shared__ float bt4_sh[32][Nc][4];   // 32 KB, assembled by all 8 CTAs
    __shared__ float node_sh[8][Hc];      // 4 KB
    __shared__ float a_sh[8][Hc];         // 4 KB
    __shared__ float x_sh[8][Fc];
    __shared__ float wv4[4][Hc];          // 2 KB wvec quarter-partials
    __shared__ float w2_sh[Hc];
    __shared__ float lp_sh[8];
    __shared__ float pr_sh[Nc];

    const int tid = threadIdx.x;
    const int b = blockIdx.x >> 3;
    uint32_t c;                           // cluster rank
    asm("mov.u32 %0, %%cluster_ctarank;" : "=r"(c));

    // DSMEM: mapa of bt4_sh base into each cluster CTA
    uint32_t bt4_u32;
    asm("{ .reg .u64 t; cvta.to.shared.u64 t, %1; cvt.u32.u64 %0, t; }"
        : "=r"(bt4_u32) : "l"(bt4_sh));
    uint32_t rem[CLUSTER];
    #pragma unroll
    for (int rk = 0; rk < CLUSTER; rk++)
        asm("mapa.shared::cluster.u32 %0, %1, %2;"
            : "=r"(rem[rk]) : "r"(bt4_u32), "r"(rk));

    // ---- stage x (8 rows x 16 f); rank 0 inits pressures to bp
    if (tid < 128) {
        int r = tid >> 4, f = tid & 15;
        int n = (int)c * 8 + r;
        x_sh[r][f] = x[(((b * Tc + (Tc - 1)) * Nc + n) * Fc) + f];
    }
    if (c == 0 && tid < Nc) out[b * Nc + tid] = __ldg(bp);
    __syncthreads();

    // ---- node: 8 rows x 128 h over 512 threads (2 outputs each)
    #pragma unroll
    for (int i = 0; i < 2; i++) {
        int idx = tid + i * NTHR;
        int r = idx >> 7, h = idx & 127;
        const float4* wg4 = (const float4*)(Wg + h * Fc);
        float4 w0 = __ldg(wg4 + 0), w1 = __ldg(wg4 + 1);
        float4 w2v= __ldg(wg4 + 2), w3 = __ldg(wg4 + 3);
        const float4* xr = (const float4*)x_sh[r];
        float4 xv[4] = { xr[0], xr[1], xr[2], xr[3] };
        node_sh[r][h] = __ldg(&bg[h]) + dot16(xv, w0, w1, w2v, w3);
    }
    __syncthreads();

    // ---- warp/lane geometry: 16 warps, warp w owns k in [w*8, w*8+8)
    const int lane = tid & 31, w = tid >> 5;
    const int j = lane & 7, d = lane >> 3;

    // ---- btT GEMM (W1t half) + DSMEM multicast stores
    {
        const float* Wt = W1 + Hc;   // W1t
        float4 wc[2][4];             // weights for kk=0,1 cached
        #pragma unroll
        for (int kk = 0; kk < 2; kk++) {
            int k = w * 8 + kk * 4 + d;
            const float4* wp4 = (const float4*)(Wt + k * (2 * Hc) + j * 16);
            wc[kk][0] = __ldg(wp4 + 0); wc[kk][1] = __ldg(wp4 + 1);
            wc[kk][2] = __ldg(wp4 + 2); wc[kk][3] = __ldg(wp4 + 3);
        }
        #pragma unroll
        for (int r = 0; r < 8; r++) {
            float4 nrs[4];
            #pragma unroll
            for (int q = 0; q < 4; q++)
                nrs[q] = *(const float4*)&node_sh[r][j * 16 + q * 4];
            #pragma unroll
            for (int kk = 0; kk < 2; kk++) {
                float acc = dot16(nrs, wc[kk][0], wc[kk][1], wc[kk][2], wc[kk][3]);
                acc += __shfl_xor_sync(0xffffffffu, acc, 1);
                acc += __shfl_xor_sync(0xffffffffu, acc, 2);
                acc += __shfl_xor_sync(0xffffffffu, acc, 4);
                if (j == 0) {
                    // bt4[k>>2][n][k&3]; k>>2 = w*2+kk, k&3 = d, n = c*8+r
                    uint32_t off = (((w * 2 + kk) * Nc) + ((int)c * 8 + r)) * 16u + d * 4u;
                    uint32_t bits = __float_as_uint(acc);
                    #pragma unroll
                    for (int rk = 0; rk < CLUSTER; rk++)
                        asm volatile("st.shared::cluster.b32 [%0], %1;"
                                     :: "r"(rem[rk] + off), "r"(bits));
                }
            }
        }
    }

    if (c == 0) __threadfence();   // publish rank0's out-init before peers' atomics

    // ---- cluster barrier ARRIVE (releases DSMEM stores)
    asm volatile("barrier.cluster.arrive.aligned;" ::: "memory");

    // ======== hidden independent work (between arrive and wait) ========
    // a GEMM (W1s) -> a_sh
    {
        const float* Ws = W1;   // W1s
        float4 wc[2][4];
        #pragma unroll
        for (int kk = 0; kk < 2; kk++) {
            int k = w * 8 + kk * 4 + d;
            const float4* wp4 = (const float4*)(Ws + k * (2 * Hc) + j * 16);
            wc[kk][0] = __ldg(wp4 + 0); wc[kk][1] = __ldg(wp4 + 1);
            wc[kk][2] = __ldg(wp4 + 2); wc[kk][3] = __ldg(wp4 + 3);
        }
        #pragma unroll
        for (int r = 0; r < 8; r++) {
            float4 nrs[4];
            #pragma unroll
            for (int q = 0; q < 4; q++)
                nrs[q] = *(const float4*)&node_sh[r][j * 16 + q * 4];
            #pragma unroll
            for (int kk = 0; kk < 2; kk++) {
                int k = w * 8 + kk * 4 + d;
                float acc = dot16(nrs, wc[kk][0], wc[kk][1], wc[kk][2], wc[kk][3]);
                acc += __shfl_xor_sync(0xffffffffu, acc, 1);
                acc += __shfl_xor_sync(0xffffffffu, acc, 2);
                acc += __shfl_xor_sync(0xffffffffu, acc, 4);
                if (j == 0) a_sh[r][k] = acc + __ldg(&b1[k]);
            }
        }
    }

    // wvec quarter-partials: thread (h = tid&127, kq = tid>>7)
    {
        int h = tid & 127, kq = tid >> 7;
        const int k0 = kq * 32;
        float s0 = 0.f, s1 = 0.f, s2 = 0.f, s3 = 0.f;
        #pragma unroll 4
        for (int k = 0; k < 32; k += 4) {
            s0 += __ldg(&Wp[k0 + k + 0]) * __ldg(&Wgcn[(k0 + k + 0) * Hc + h]);
            s1 += __ldg(&Wp[k0 + k + 1]) * __ldg(&Wgcn[(k0 + k + 1) * Hc + h]);
            s2 += __ldg(&Wp[k0 + k + 2]) * __ldg(&Wgcn[(k0 + k + 2) * Hc + h]);
            s3 += __ldg(&Wp[k0 + k + 3]) * __ldg(&Wgcn[(k0 + k + 3) * Hc + h]);
        }
        wv4[kq][h] = (s0 + s1) + (s2 + s3);
    }
    if (tid < 128) w2_sh[tid] = __ldg(&W2[tid]);
    if (tid < Nc)  pr_sh[tid] = 0.f;
    __syncthreads();

    // lp: warps 0..7 reduce node row w against wvec; cb folded inline
    if (w < 8) {
        int h4 = lane * 4;
        float4 n  = *(const float4*)&node_sh[w][h4];
        float4 q0 = *(const float4*)&wv4[0][h4];
        float4 q1 = *(const float4*)&wv4[1][h4];
        float4 q2 = *(const float4*)&wv4[2][h4];
        float4 q3 = *(const float4*)&wv4[3][h4];
        float4 wp = __ldg((const float4*)(Wp   + h4) );
        float4 bc = __ldg((const float4*)(bgcn + h4) );
        float p0 = n.x*(q0.x+q1.x+q2.x+q3.x) + wp.x*bc.x;
        float p1 = n.y*(q0.y+q1.y+q2.y+q3.y) + wp.y*bc.y;
        float p2 = n.z*(q0.z+q1.z+q2.z+q3.z) + wp.z*bc.z;
        float p3 = n.w*(q0.w+q1.w+q2.w+q3.w) + wp.w*bc.w;
        float v = (p0 + p1) + (p2 + p3);
        #pragma unroll
        for (int o = 16; o; o >>= 1) v += __shfl_xor_sync(0xffffffffu, v, o);
        if (lane == 0) lp_sh[w] = v;
    }

    // ---- cluster barrier WAIT (acquires all 8 CTAs' DSMEM stores)
    asm volatile("barrier.cluster.wait.aligned;" ::: "memory");
    __syncthreads();   // lp_sh / a_sh visible block-wide

    // ---- dense edge loop: warp = (sl = w>>1, th = w&1); lane -> t
    {
        const int sl = w >> 1;                // 0..7 local src
        const int t  = (w & 1) * 32 + lane;   // 0..63
        const int s  = (int)c * 8 + sl;       // global src

        float ax = 0.f, ay = 0.f, az = 0.f, aw = 0.f;
        #pragma unroll 8
        for (int kq = 0; kq < 32; kq++) {
            float4 a4 = *(const float4*)&a_sh[sl][kq * 4];    // broadcast
            float4 w4 = *(const float4*)&w2_sh[kq * 4];       // broadcast
            float4 bt = *(const float4*)&bt4_sh[kq][t][0];    // conflict-free
            ax += fmaxf(a4.x + bt.x, 0.f) * w4.x;
            ay += fmaxf(a4.y + bt.y, 0.f) * w4.y;
            az += fmaxf(a4.z + bt.z, 0.f) * w4.z;
            aw += fmaxf(a4.w + bt.w, 0.f) * w4.w;
        }
        float acc = (ax + ay) + (az + aw);

        if (t != s) {
            float ew = acc + __ldg(b2);
            int e = s * 63 + (t < s ? t : t - 1);
            out[BN + b * E + e] = ew;
            atomicAdd(&pr_sh[t], ew * lp_sh[sl]);
        }
    }
    __syncthreads();
    if (tid < Nc) atomicAdd(out + b * Nc + tid, pr_sh[tid]);
}

// ---------------------------------------------------------------------------
extern "C" void kernel_launch(void* const* d_in, const int* in_sizes, int n_in,
                              void* d_out, int out_size)
{
    const float* x    = (const float*)d_in[0];
    const float* Wg   = (const float*)d_in[2];
    const float* bg   = (const float*)d_in[3];
    const float* W1   = (const float*)d_in[4];
    const float* b1   = (const float*)d_in[5];
    const float* W2   = (const float*)d_in[6];
    const float* b2   = (const float*)d_in[7];
    const float* Wgcn = (const float*)d_in[8];
    const float* bgcn = (const float*)d_in[9];
    const float* Wp   = (const float*)d_in[14];
    const float* bp   = (const float*)d_in[15];
    float* out = (float*)d_out;

    const int E = in_sizes[1] / 2;   // 4032 = 64*63 (dense permutations)

    kfused<<<GRID, NTHR>>>(x, Wg, bg, W1, b1, W2, b2,
                           Wgcn, bgcn, Wp, bp, out, E);
}

// round 11
// speedup vs baseline: 1.3433x; 1.3433x over previous
#include <cuda_runtime.h>

// Problem constants (STGNN_91242285236402): B=8, T=16, N=64, F=16, H=128
#define Bc 8
#define Tc 16
#define Nc 64
#define Fc 16
#define Hc 128
#define BN (Bc * Nc)   // 512
#define GRID 128
#define NTHR 256

// Scratch (allocation-free): btT in k-vectorized layout [b][k>>2][n][k&3]
__device__ float g_bt4[Bc * 32 * Nc * 4];

// Two-level barrier: 8 batch counters (16 arrivals each) + 1 root (8 arrivals).
// All monotonic (replay-safe). 256B stride to land in distinct L2 slices.
struct Cnt { unsigned c; unsigned pad[63]; };
__device__ Cnt g_batch[Bc];
__device__ __align__(256) unsigned g_root = 0;

// ---------------------------------------------------------------------------
// One fused kernel, 128 blocks x 256 threads (all co-resident on 148 SMs).
// Block (b = blockIdx>>4, g = blockIdx&15) owns rows rowbase = blockIdx*4,
// which are BOTH its Phase-A produce set and its Phase-B source nodes.
//   pre-arrive : node[4][128]; btT GEMM (W1t) -> g_bt4 (global)
//   arrive     : fence; ticket = add(g_batch[b]); last-of-16 -> fence; add(root)
//   hidden work: a GEMM (W1s) -> smem; wvec (Wgcn.T@Wp); cb; lp; w2; pr init
//   wait       : poll root >= 8*(epoch+1)  (FULL-GRID release, as proven)
//   post       : stage g_bt4[b] -> smem; dense edge loop:
//     ew(s,t) = b2 + sum_k relu(a[s,k] + btT[k,t]) * W2[k], e = s*63+(t-(t>s))
//     pressures[b,t] += ew * lp[s]
// ---------------------------------------------------------------------------
__global__ void __launch_bounds__(NTHR) kfused(
    const float* __restrict__ x,   const float* __restrict__ Wg,
    const float* __restrict__ bg,  const float* __restrict__ W1,
    const float* __restrict__ b1,  const float* __restrict__ W2,
    const float* __restrict__ b2,  const float* __restrict__ Wgcn,
    const float* __restrict__ bgcn,const float* __restrict__ Wp,
    const float* __restrict__ bp,  float* __restrict__ out, int E)
{
    __shared__ float x_sh[4][Fc];
    __shared__ float node_sh[4][Hc];
    __shared__ float a_sh[4][Hc];
    __shared__ float wv2[2][Hc];
    __shared__ float w2_sh[Hc];
    __shared__ float lp_sh[4];
    __shared__ float pr_sh[Nc];
    __shared__ float bt4_sh[32][Nc][4];   // 32 KB
    __shared__ unsigned s_target;
    __shared__ float cb_sh;

    const int tid = threadIdx.x;
    const int b = blockIdx.x >> 4;
    const int g = blockIdx.x & 15;
    const int rowbase = blockIdx.x * 4;   // = b*64 + g*4

    // ---- stage x (4 rows x 16 f); init pressures (g==0 blocks); cb init
    if (tid < 64) {
        int r = tid >> 4, f = tid & 15;
        int n = (rowbase + r) & 63;
        x_sh[r][f] = x[(((b * Tc + (Tc - 1)) * Nc + n) * Fc) + f];
    }
    if (g == 0 && tid < Nc) out[b * Nc + tid] = __ldg(bp);
    if (tid == 0) cb_sh = 0.f;
    __syncthreads();

    // ---- node: 4 rows x 128 h over 256 threads (2 outputs each)
    #pragma unroll
    for (int i = 0; i < 2; i++) {
        int idx = tid + i * NTHR;
        int r = idx >> 7, h = idx & 127;
        const float4* wg4 = (const float4*)(Wg + h * Fc);
        float4 w0 = __ldg(wg4 + 0), w1 = __ldg(wg4 + 1);
        float4 w2v= __ldg(wg4 + 2), w3 = __ldg(wg4 + 3);
        const float* xr = x_sh[r];
        float acc = __ldg(&bg[h]);
        acc += xr[0]*w0.x + xr[1]*w0.y + xr[2]*w0.z + xr[3]*w0.w;
        acc += xr[4]*w1.x + xr[5]*w1.y + xr[6]*w1.z + xr[7]*w1.w;
        acc += xr[8]*w2v.x+ xr[9]*w2v.y+ xr[10]*w2v.z+ xr[11]*w2v.w;
        acc += xr[12]*w3.x+ xr[13]*w3.y+ xr[14]*w3.z+ xr[15]*w3.w;
        node_sh[r][h] = acc;
    }
    __syncthreads();

    // ---- cache node[4 rows][j*16..+16] in registers (16 float4)
    const int lane = tid & 31, w = tid >> 5;
    const int j = lane & 7, d = lane >> 3;
    float4 nr[4][4];
    #pragma unroll
    for (int r = 0; r < 4; r++)
        #pragma unroll
        for (int c = 0; c < 4; c++)
            nr[r][c] = *(const float4*)&node_sh[r][j * 16 + c * 4];

    // ---- btT GEMM (W1t half): warp w -> k in [w*16,+16); 8-lane dots
    {
        const float* Wt = W1 + Hc;   // W1t
        #pragma unroll
        for (int kk = 0; kk < 4; kk++) {
            int k = w * 16 + kk * 4 + d;
            const float4* wp4 = (const float4*)(Wt + k * (2 * Hc) + j * 16);
            float4 w0 = __ldg(wp4 + 0), w1 = __ldg(wp4 + 1);
            float4 w2v= __ldg(wp4 + 2), w3 = __ldg(wp4 + 3);
            #pragma unroll
            for (int r = 0; r < 4; r++) {
                float acc = nr[r][0].x*w0.x + nr[r][0].y*w0.y + nr[r][0].z*w0.z + nr[r][0].w*w0.w
                          + nr[r][1].x*w1.x + nr[r][1].y*w1.y + nr[r][1].z*w1.z + nr[r][1].w*w1.w
                          + nr[r][2].x*w2v.x+ nr[r][2].y*w2v.y+ nr[r][2].z*w2v.z+ nr[r][2].w*w2v.w
                          + nr[r][3].x*w3.x + nr[r][3].y*w3.y + nr[r][3].z*w3.z + nr[r][3].w*w3.w;
                acc += __shfl_xor_sync(0xffffffffu, acc, 1);
                acc += __shfl_xor_sync(0xffffffffu, acc, 2);
                acc += __shfl_xor_sync(0xffffffffu, acc, 4);
                if (j == 0) {
                    int n = g * 4 + r;
                    g_bt4[((b * 32 + (w * 4 + kk)) * Nc + n) * 4 + d] = acc;
                }
            }
        }
    }

    // ---- barrier ARRIVE: batch counter ticket; last-of-16 arrives at root
    __syncthreads();                        // all g_bt4 stores issued
    if (tid == 0) {
        __threadfence();                    // publish stores before arrival
        unsigned v = atomicAdd(&g_batch[b].c, 1u);
        unsigned epoch = v >> 4;            // exactly 16/batch/launch
        if ((v & 15u) == 15u) {             // last arriver of this batch
            __threadfence();                // order batch observation -> root
            atomicAdd(&g_root, 1u);
        }
        s_target = (epoch + 1u) * 8u;       // root gets exactly 8/launch
    }

    // ---- hidden independent work: a GEMM (W1s) -> a_sh
    {
        const float* Ws = W1;   // W1s
        #pragma unroll
        for (int kk = 0; kk < 4; kk++) {
            int k = w * 16 + kk * 4 + d;
            const float4* wp4 = (const float4*)(Ws + k * (2 * Hc) + j * 16);
            float4 w0 = __ldg(wp4 + 0), w1 = __ldg(wp4 + 1);
            float4 w2v= __ldg(wp4 + 2), w3 = __ldg(wp4 + 3);
            #pragma unroll
            for (int r = 0; r < 4; r++) {
                float acc = nr[r][0].x*w0.x + nr[r][0].y*w0.y + nr[r][0].z*w0.z + nr[r][0].w*w0.w
                          + nr[r][1].x*w1.x + nr[r][1].y*w1.y + nr[r][1].z*w1.z + nr[r][1].w*w1.w
                          + nr[r][2].x*w2v.x+ nr[r][2].y*w2v.y+ nr[r][2].z*w2v.z+ nr[r][2].w*w2v.w
                          + nr[r][3].x*w3.x + nr[r][3].y*w3.y + nr[r][3].z*w3.z + nr[r][3].w*w3.w;
                acc += __shfl_xor_sync(0xffffffffu, acc, 1);
                acc += __shfl_xor_sync(0xffffffffu, acc, 2);
                acc += __shfl_xor_sync(0xffffffffu, acc, 4);
                if (j == 0) a_sh[r][k] = acc + __ldg(&b1[k]);
            }
        }
    }

    // ---- wvec half-partials + cb (all local)
    {
        int h = tid & 127, kh = tid >> 7;
        float s = 0.f;
        const int k0 = kh * 64;
        #pragma unroll 16
        for (int k = 0; k < 64; k++)
            s += __ldg(&Wp[k0 + k]) * __ldg(&Wgcn[(k0 + k) * Hc + h]);
        wv2[kh][h] = s;
    }
    if (tid < 128) {
        float v = __ldg(&Wp[tid]) * __ldg(&bgcn[tid]);
        #pragma unroll
        for (int o = 16; o; o >>= 1) v += __shfl_xor_sync(0xffffffffu, v, o);
        if ((tid & 31) == 0) atomicAdd(&cb_sh, v);
    }
    if (tid < 128) w2_sh[tid] = __ldg(&W2[tid]);
    if (tid < Nc)  pr_sh[tid] = 0.f;
    __syncthreads();

    // lp: warps 0..3 reduce node rows 0..3 against wvec
    if (w < 4) {
        float4 n  = *(const float4*)&node_sh[w][lane * 4];
        float4 wa = *(const float4*)&wv2[0][lane * 4];
        float4 wb = *(const float4*)&wv2[1][lane * 4];
        float v = n.x*(wa.x+wb.x) + n.y*(wa.y+wb.y)
                + n.z*(wa.z+wb.z) + n.w*(wa.w+wb.w);
        #pragma unroll
        for (int o = 16; o; o >>= 1) v += __shfl_xor_sync(0xffffffffu, v, o);
        if (lane == 0) lp_sh[w] = v + cb_sh;
    }

    // ---- barrier WAIT: poll ROOT (full-grid release)
    __syncthreads();                        // s_target visible; local work done
    if (tid == 0) {
        volatile unsigned* p = &g_root;
        while (*p < s_target) __nanosleep(32);
        __threadfence();                    // acquire
    }
    __syncthreads();

    // ---- stage g_bt4[b] (32 KB) -> bt4_sh
    {
        const float4* src4 = (const float4*)(g_bt4 + b * 32 * Nc * 4);
        #pragma unroll
        for (int p = 0; p < 8; p++) {
            int q = tid + p * NTHR;          // 0..2047
            int k4 = q >> 6, t4 = q & 63;
            *(float4*)&bt4_sh[k4][t4][0] = __ldg(src4 + q);
        }
    }
    __syncthreads();

    // ---- dense edge loop: warp = (sl = w>>1, th = w&1); lane -> t
    {
        const int sl = w >> 1;
        const int t  = (w & 1) * 32 + lane;
        const int s  = g * 4 + sl;

        float acc = 0.f;
        #pragma unroll 8
        for (int kq = 0; kq < 32; kq++) {
            float4 a4 = *(const float4*)&a_sh[sl][kq * 4];    // broadcast
            float4 w4 = *(const float4*)&w2_sh[kq * 4];       // broadcast
            float4 bt = *(const float4*)&bt4_sh[kq][t][0];    // conflict-free
            acc += fmaxf(a4.x + bt.x, 0.f) * w4.x;
            acc += fmaxf(a4.y + bt.y, 0.f) * w4.y;
            acc += fmaxf(a4.z + bt.z, 0.f) * w4.z;
            acc += fmaxf(a4.w + bt.w, 0.f) * w4.w;
        }

        if (t != s) {
            float ew = acc + __ldg(b2);
            int e = s * 63 + (t < s ? t : t - 1);
            out[BN + b * E + e] = ew;
            atomicAdd(&pr_sh[t], ew * lp_sh[sl]);
        }
    }
    __syncthreads();
    if (tid < Nc) atomicAdd(out + b * Nc + tid, pr_sh[tid]);
}

// ---------------------------------------------------------------------------
extern "C" void kernel_launch(void* const* d_in, const int* in_sizes, int n_in,
                              void* d_out, int out_size)
{
    const float* x    = (const float*)d_in[0];
    const float* Wg   = (const float*)d_in[2];
    const float* bg   = (const float*)d_in[3];
    const float* W1   = (const float*)d_in[4];
    const float* b1   = (const float*)d_in[5];
    const float* W2   = (const float*)d_in[6];
    const float* b2   = (const float*)d_in[7];
    const float* Wgcn = (const float*)d_in[8];
    const float* bgcn = (const float*)d_in[9];
    const float* Wp   = (const float*)d_in[14];
    const float* bp   = (const float*)d_in[15];
    float* out = (float*)d_out;

    const int E = in_sizes[1] / 2;   // 4032 = 64*63 (dense permutations)

    kfused<<<GRID, NTHR>>>(x, Wg, bg, W1, b1, W2, b2,
                           Wgcn, bgcn, Wp, bp, out, E);
}

// round 12
// speedup vs baseline: 1.5517x; 1.1552x over previous
#include <cuda_runtime.h>

// Problem constants (STGNN_91242285236402): B=8, T=16, N=64, F=16, H=128
#define Bc 8
#define Tc 16
#define Nc 64
#define Fc 16
#define Hc 128
#define BN (Bc * Nc)   // 512
#define GRID 128
#define NTHR 256

// Scratch (allocation-free): btT in k-vectorized layout [b][k>>2][n][k&3]
__device__ float g_bt4[Bc * 32 * Nc * 4];
__device__ unsigned g_bar = 0;          // grid barrier (monotonic, replay-safe)

// ---------------------------------------------------------------------------
// One fused kernel, 128 blocks x 256 threads (all co-resident on 148 SMs).
// Block (b = blockIdx>>4, g = blockIdx&15) owns rows rowbase = blockIdx*4,
// which are BOTH its Phase-A produce set and its Phase-B source nodes.
//   pre-arrive : node[4][128]; btT GEMM (W1t) -> g_bt4 (global)
//   arrive     : grid-barrier ticket (proven monotonic pattern)
//   hidden work: a GEMM (W1s) -> smem; wvec partials (vectorized); cb; lp;
//                w2 stage; pr init
//   wait       : spin to wave target
//   post       : dense edge loop reading g_bt4 DIRECTLY (coalesced L2 hits):
//     ew(s,t) = b2 + sum_k relu(a[s,k] + btT[k,t]) * W2[k], e = s*63+(t-(t>s))
//     pressures[b,t] += ew * lp[s]
// ---------------------------------------------------------------------------
__global__ void __launch_bounds__(NTHR) kfused(
    const float* __restrict__ x,   const float* __restrict__ Wg,
    const float* __restrict__ bg,  const float* __restrict__ W1,
    const float* __restrict__ b1,  const float* __restrict__ W2,
    const float* __restrict__ b2,  const float* __restrict__ Wgcn,
    const float* __restrict__ bgcn,const float* __restrict__ Wp,
    const float* __restrict__ bp,  float* __restrict__ out, int E)
{
    __shared__ float x_sh[4][Fc];
    __shared__ float node_sh[4][Hc];
    __shared__ float a_sh[4][Hc];
    __shared__ float wv8[8][Hc];    // wvec partials per 16-k group (4 KB)
    __shared__ float w2_sh[Hc];
    __shared__ float lp_sh[4];
    __shared__ float pr_sh[Nc];
    __shared__ unsigned s_target;
    __shared__ float cb_sh;

    const int tid = threadIdx.x;
    const int b = blockIdx.x >> 4;
    const int g = blockIdx.x & 15;
    const int rowbase = blockIdx.x * 4;   // = b*64 + g*4

    // ---- stage x (4 rows x 16 f); init pressures (g==0 blocks); cb init
    if (tid < 64) {
        int r = tid >> 4, f = tid & 15;
        int n = (rowbase + r) & 63;
        x_sh[r][f] = x[(((b * Tc + (Tc - 1)) * Nc + n) * Fc) + f];
    }
    if (g == 0 && tid < Nc) out[b * Nc + tid] = __ldg(bp);
    if (tid == 0) cb_sh = 0.f;
    __syncthreads();

    // ---- node: 4 rows x 128 h over 256 threads (2 outputs each)
    #pragma unroll
    for (int i = 0; i < 2; i++) {
        int idx = tid + i * NTHR;
        int r = idx >> 7, h = idx & 127;
        const float4* wg4 = (const float4*)(Wg + h * Fc);
        float4 w0 = __ldg(wg4 + 0), w1 = __ldg(wg4 + 1);
        float4 w2v= __ldg(wg4 + 2), w3 = __ldg(wg4 + 3);
        const float* xr = x_sh[r];
        float acc = __ldg(&bg[h]);
        acc += xr[0]*w0.x + xr[1]*w0.y + xr[2]*w0.z + xr[3]*w0.w;
        acc += xr[4]*w1.x + xr[5]*w1.y + xr[6]*w1.z + xr[7]*w1.w;
        acc += xr[8]*w2v.x+ xr[9]*w2v.y+ xr[10]*w2v.z+ xr[11]*w2v.w;
        acc += xr[12]*w3.x+ xr[13]*w3.y+ xr[14]*w3.z+ xr[15]*w3.w;
        node_sh[r][h] = acc;
    }
    __syncthreads();

    // ---- cache node[4 rows][j*16..+16] in registers (16 float4)
    const int lane = tid & 31, w = tid >> 5;
    const int j = lane & 7, d = lane >> 3;
    float4 nr[4][4];
    #pragma unroll
    for (int r = 0; r < 4; r++)
        #pragma unroll
        for (int c = 0; c < 4; c++)
            nr[r][c] = *(const float4*)&node_sh[r][j * 16 + c * 4];

    // ---- btT GEMM (W1t half): warp w -> k in [w*16,+16); 8-lane dots
    {
        const float* Wt = W1 + Hc;   // W1t
        #pragma unroll
        for (int kk = 0; kk < 4; kk++) {
            int k = w * 16 + kk * 4 + d;
            const float4* wp4 = (const float4*)(Wt + k * (2 * Hc) + j * 16);
            float4 w0 = __ldg(wp4 + 0), w1 = __ldg(wp4 + 1);
            float4 w2v= __ldg(wp4 + 2), w3 = __ldg(wp4 + 3);
            #pragma unroll
            for (int r = 0; r < 4; r++) {
                float acc = nr[r][0].x*w0.x + nr[r][0].y*w0.y + nr[r][0].z*w0.z + nr[r][0].w*w0.w
                          + nr[r][1].x*w1.x + nr[r][1].y*w1.y + nr[r][1].z*w1.z + nr[r][1].w*w1.w
                          + nr[r][2].x*w2v.x+ nr[r][2].y*w2v.y+ nr[r][2].z*w2v.z+ nr[r][2].w*w2v.w
                          + nr[r][3].x*w3.x + nr[r][3].y*w3.y + nr[r][3].z*w3.z + nr[r][3].w*w3.w;
                acc += __shfl_xor_sync(0xffffffffu, acc, 1);
                acc += __shfl_xor_sync(0xffffffffu, acc, 2);
                acc += __shfl_xor_sync(0xffffffffu, acc, 4);
                if (j == 0) {
                    int n = g * 4 + r;
                    g_bt4[((b * 32 + (w * 4 + kk)) * Nc + n) * 4 + d] = acc;
                }
            }
        }
    }

    // ---- barrier ARRIVE (proven monotonic pattern, split arrive/wait)
    __syncthreads();                        // all g_bt4 stores issued
    if (tid == 0) {
        __threadfence();                    // publish before arrival
        unsigned v = atomicAdd(&g_bar, 1u);
        s_target = (v & ~(GRID - 1u)) + GRID;
    }

    // ---- hidden independent work: a GEMM (W1s) -> a_sh
    {
        const float* Ws = W1;   // W1s
        #pragma unroll
        for (int kk = 0; kk < 4; kk++) {
            int k = w * 16 + kk * 4 + d;
            const float4* wp4 = (const float4*)(Ws + k * (2 * Hc) + j * 16);
            float4 w0 = __ldg(wp4 + 0), w1 = __ldg(wp4 + 1);
            float4 w2v= __ldg(wp4 + 2), w3 = __ldg(wp4 + 3);
            #pragma unroll
            for (int r = 0; r < 4; r++) {
                float acc = nr[r][0].x*w0.x + nr[r][0].y*w0.y + nr[r][0].z*w0.z + nr[r][0].w*w0.w
                          + nr[r][1].x*w1.x + nr[r][1].y*w1.y + nr[r][1].z*w1.z + nr[r][1].w*w1.w
                          + nr[r][2].x*w2v.x+ nr[r][2].y*w2v.y+ nr[r][2].z*w2v.z+ nr[r][2].w*w2v.w
                          + nr[r][3].x*w3.x + nr[r][3].y*w3.y + nr[r][3].z*w3.z + nr[r][3].w*w3.w;
                acc += __shfl_xor_sync(0xffffffffu, acc, 1);
                acc += __shfl_xor_sync(0xffffffffu, acc, 2);
                acc += __shfl_xor_sync(0xffffffffu, acc, 4);
                if (j == 0) a_sh[r][k] = acc + __ldg(&b1[k]);
            }
        }
    }

    // ---- wvec partials, vectorized: thread = (kq = tid>>5, hq = tid&31)
    //      16 iters x (1 coalesced LDG.128 + 1 scalar) instead of 128 scalars
    {
        int hq = tid & 31, kq = tid >> 5;
        const int k0 = kq * 16;
        float4 s = make_float4(0.f, 0.f, 0.f, 0.f);
        #pragma unroll
        for (int k = 0; k < 16; k++) {
            float wp = __ldg(&Wp[k0 + k]);
            float4 gv = __ldg((const float4*)(Wgcn + (k0 + k) * Hc) + hq);
            s.x += wp * gv.x; s.y += wp * gv.y;
            s.z += wp * gv.z; s.w += wp * gv.w;
        }
        *(float4*)&wv8[kq][hq * 4] = s;
    }
    if (tid < 128) {
        float v = __ldg(&Wp[tid]) * __ldg(&bgcn[tid]);
        #pragma unroll
        for (int o = 16; o; o >>= 1) v += __shfl_xor_sync(0xffffffffu, v, o);
        if ((tid & 31) == 0) atomicAdd(&cb_sh, v);
    }
    if (tid < 128) w2_sh[tid] = __ldg(&W2[tid]);
    if (tid < Nc)  pr_sh[tid] = 0.f;
    __syncthreads();

    // lp: warps 0..3 reduce node rows 0..3 against wvec (8 partials inline)
    if (w < 4) {
        int h4 = lane * 4;
        float4 n = *(const float4*)&node_sh[w][h4];
        float4 q = *(const float4*)&wv8[0][h4];
        #pragma unroll
        for (int kq = 1; kq < 8; kq++) {
            float4 t = *(const float4*)&wv8[kq][h4];
            q.x += t.x; q.y += t.y; q.z += t.z; q.w += t.w;
        }
        float p0 = n.x*q.x, p1 = n.y*q.y, p2 = n.z*q.z, p3 = n.w*q.w;
        float v = (p0 + p1) + (p2 + p3);
        #pragma unroll
        for (int o = 16; o; o >>= 1) v += __shfl_xor_sync(0xffffffffu, v, o);
        if (lane == 0) lp_sh[w] = v + cb_sh;
    }

    // ---- barrier WAIT
    __syncthreads();                        // s_target visible; local work done
    if (tid == 0) {
        volatile unsigned* p = &g_bar;
        while (*p < s_target) __nanosleep(32);
        __threadfence();                    // acquire
    }
    __syncthreads();

    // ---- dense edge loop: warp = (sl = w>>1, th = w&1); lane -> t
    //      bt read DIRECTLY from g_bt4 (coalesced float4 per kq, L2 hits)
    {
        const int sl = w >> 1;
        const int t  = (w & 1) * 32 + lane;
        const int s  = g * 4 + sl;
        const float4* btp = (const float4*)g_bt4 + (b * 32) * Nc + t;

        float acc = 0.f;
        #pragma unroll 8
        for (int kq = 0; kq < 32; kq++) {
            float4 a4 = *(const float4*)&a_sh[sl][kq * 4];    // broadcast
            float4 w4 = *(const float4*)&w2_sh[kq * 4];       // broadcast
            float4 bt = __ldg(btp + kq * Nc);                 // coalesced
            acc += fmaxf(a4.x + bt.x, 0.f) * w4.x;
            acc += fmaxf(a4.y + bt.y, 0.f) * w4.y;
            acc += fmaxf(a4.z + bt.z, 0.f) * w4.z;
            acc += fmaxf(a4.w + bt.w, 0.f) * w4.w;
        }

        if (t != s) {
            float ew = acc + __ldg(b2);
            int e = s * 63 + (t < s ? t : t - 1);
            out[BN + b * E + e] = ew;
            atomicAdd(&pr_sh[t], ew * lp_sh[sl]);
        }
    }
    __syncthreads();
    if (tid < Nc) atomicAdd(out + b * Nc + tid, pr_sh[tid]);
}

// ---------------------------------------------------------------------------
extern "C" void kernel_launch(void* const* d_in, const int* in_sizes, int n_in,
                              void* d_out, int out_size)
{
    const float* x    = (const float*)d_in[0];
    const float* Wg   = (const float*)d_in[2];
    const float* bg   = (const float*)d_in[3];
    const float* W1   = (const float*)d_in[4];
    const float* b1   = (const float*)d_in[5];
    const float* W2   = (const float*)d_in[6];
    const float* b2   = (const float*)d_in[7];
    const float* Wgcn = (const float*)d_in[8];
    const float* bgcn = (const float*)d_in[9];
    const float* Wp   = (const float*)d_in[14];
    const float* bp   = (const float*)d_in[15];
    float* out = (float*)d_out;

    const int E = in_sizes[1] / 2;   // 4032 = 64*63 (dense permutations)

    kfused<<<GRID, NTHR>>>(x, Wg, bg, W1, b1, W2, b2,
                           Wgcn, bgcn, Wp, bp, out, E);
}